// round 1
// baseline (speedup 1.0000x reference)
#include <cuda_runtime.h>

#define CI 16
#define CO 16

// Pre-fused, lane-duplicated weights/biases (prep kernel fills these).
// W1 = Wa @ Wt  (fused first two linears), b1 = Wa @ bt + ba
// W2 = Wb,      b2 = bb
__device__ float2 g_W1[CO * CI];
__device__ float2 g_W2[CO * CO];
__device__ float2 g_b1[CO];
__device__ float2 g_b2[CO];

__global__ void prep_kernel(const float* __restrict__ Wt, const float* __restrict__ bt,
                            const float* __restrict__ Wa, const float* __restrict__ ba,
                            const float* __restrict__ Wb, const float* __restrict__ bb)
{
    int t = threadIdx.x;              // 256 threads, t = j*16 + i
    int j = t >> 4;
    int i = t & 15;

    // W1[j][i] = sum_o Wa[j][o] * Wt[o][i]
    float w = 0.0f;
#pragma unroll
    for (int o = 0; o < CO; ++o)
        w = fmaf(Wa[j * CO + o], Wt[o * CI + i], w);
    g_W1[j * CI + i] = make_float2(w, w);

    float w2 = Wb[j * CO + i];
    g_W2[j * CO + i] = make_float2(w2, w2);

    if (i == 0) {
        float b = ba[j];
#pragma unroll
        for (int o = 0; o < CO; ++o)
            b = fmaf(Wa[j * CO + o], bt[o], b);
        g_b1[j] = make_float2(b, b);
        float b2 = bb[j];
        g_b2[j] = make_float2(b2, b2);
    }
}

// Packed dual-fp32 FMA (sm_100+). ptxas never emits this from C++; inline PTX only.
__device__ __forceinline__ float2 ffma2(float2 a, float2 b, float2 c)
{
    unsigned long long au, bu, cu, du;
    au = *reinterpret_cast<unsigned long long*>(&a);
    bu = *reinterpret_cast<unsigned long long*>(&b);
    cu = *reinterpret_cast<unsigned long long*>(&c);
    asm("fma.rn.f32x2 %0, %1, %2, %3;" : "=l"(du) : "l"(au), "l"(bu), "l"(cu));
    float2 d = *reinterpret_cast<float2*>(&du);
    return d;
}

__global__ void __launch_bounds__(256)
dmasif_main_kernel(const float* __restrict__ X, float* __restrict__ Y,
                   int npairs, int N)
{
    __shared__ float2 sW1[CO * CI];
    __shared__ float2 sW2[CO * CO];
    __shared__ float2 sb1[CO];
    __shared__ float2 sb2[CO];

    int tid = threadIdx.x;
    // stage weights to SMEM (broadcast-friendly)
    sW1[tid] = g_W1[tid];
    sW2[tid] = g_W2[tid];
    if (tid < CO) { sb1[tid] = g_b1[tid]; sb2[tid] = g_b2[tid]; }
    __syncthreads();

    int t = blockIdx.x * 256 + tid;
    if (t >= npairs) return;

    long long rowA = 2LL * t;
    long long rowB = rowA + 1;
    bool hasB = (rowB < N);
    if (!hasB) rowB = rowA;   // duplicate row for the odd tail (N is even here anyway)

    const float4* pA = reinterpret_cast<const float4*>(X + rowA * CI);
    const float4* pB = reinterpret_cast<const float4*>(X + rowB * CI);

    float4 a0 = pA[0], a1 = pA[1], a2 = pA[2], a3 = pA[3];
    float4 c0 = pB[0], c1 = pB[1], c2 = pB[2], c3 = pB[3];

    // Pack the two points lane-wise: x2[i] = { A[i], B[i] }
    float2 x2[CI];
    x2[0]  = make_float2(a0.x, c0.x); x2[1]  = make_float2(a0.y, c0.y);
    x2[2]  = make_float2(a0.z, c0.z); x2[3]  = make_float2(a0.w, c0.w);
    x2[4]  = make_float2(a1.x, c1.x); x2[5]  = make_float2(a1.y, c1.y);
    x2[6]  = make_float2(a1.z, c1.z); x2[7]  = make_float2(a1.w, c1.w);
    x2[8]  = make_float2(a2.x, c2.x); x2[9]  = make_float2(a2.y, c2.y);
    x2[10] = make_float2(a2.z, c2.z); x2[11] = make_float2(a2.w, c2.w);
    x2[12] = make_float2(a3.x, c3.x); x2[13] = make_float2(a3.y, c3.y);
    x2[14] = make_float2(a3.z, c3.z); x2[15] = make_float2(a3.w, c3.w);

    // ---- GEMM1 (fused Wt->Wa): acc = x @ W1^T + b1 ----
    float2 acc[CO];
#pragma unroll
    for (int j = 0; j < CO; ++j) acc[j] = sb1[j];

    const float4* W1v = reinterpret_cast<const float4*>(sW1);  // 2 dup-weights per float4
#pragma unroll
    for (int j = 0; j < CO; ++j) {
#pragma unroll
        for (int i2 = 0; i2 < CI / 2; ++i2) {
            float4 w = W1v[j * (CI / 2) + i2];          // LDS.128: {W[j][2i],W[j][2i],W[j][2i+1],W[j][2i+1]}
            acc[j] = ffma2(x2[2 * i2 + 0], make_float2(w.x, w.y), acc[j]);
            acc[j] = ffma2(x2[2 * i2 + 1], make_float2(w.z, w.w), acc[j]);
        }
    }

    // ---- ReLU (per lane) ----
#pragma unroll
    for (int j = 0; j < CO; ++j) {
        acc[j].x = fmaxf(acc[j].x, 0.0f);
        acc[j].y = fmaxf(acc[j].y, 0.0f);
    }

    // ---- GEMM2: out = acc @ Wb^T + bb ----
    float2 out[CO];
#pragma unroll
    for (int m = 0; m < CO; ++m) out[m] = sb2[m];

    const float4* W2v = reinterpret_cast<const float4*>(sW2);
#pragma unroll
    for (int m = 0; m < CO; ++m) {
#pragma unroll
        for (int j2 = 0; j2 < CO / 2; ++j2) {
            float4 w = W2v[m * (CO / 2) + j2];
            out[m] = ffma2(acc[2 * j2 + 0], make_float2(w.x, w.y), out[m]);
            out[m] = ffma2(acc[2 * j2 + 1], make_float2(w.z, w.w), out[m]);
        }
    }

    // ---- Store both rows (vectorized) ----
    float4* yA = reinterpret_cast<float4*>(Y + rowA * CO);
    yA[0] = make_float4(out[0].x,  out[1].x,  out[2].x,  out[3].x);
    yA[1] = make_float4(out[4].x,  out[5].x,  out[6].x,  out[7].x);
    yA[2] = make_float4(out[8].x,  out[9].x,  out[10].x, out[11].x);
    yA[3] = make_float4(out[12].x, out[13].x, out[14].x, out[15].x);

    if (hasB) {
        float4* yB = reinterpret_cast<float4*>(Y + rowB * CO);
        yB[0] = make_float4(out[0].y,  out[1].y,  out[2].y,  out[3].y);
        yB[1] = make_float4(out[4].y,  out[5].y,  out[6].y,  out[7].y);
        yB[2] = make_float4(out[8].y,  out[9].y,  out[10].y, out[11].y);
        yB[3] = make_float4(out[12].y, out[13].y, out[14].y, out[15].y);
    }
}

extern "C" void kernel_launch(void* const* d_in, const int* in_sizes, int n_in,
                              void* d_out, int out_size)
{
    // input order: features, points, nuv, Wt, bt, Wa, ba, Wb, bb, ranges
    const float* features = (const float*)d_in[0];
    const float* Wt = (const float*)d_in[3];
    const float* bt = (const float*)d_in[4];
    const float* Wa = (const float*)d_in[5];
    const float* ba = (const float*)d_in[6];
    const float* Wb = (const float*)d_in[7];
    const float* bb = (const float*)d_in[8];
    float* out = (float*)d_out;

    int N = in_sizes[0] / CI;
    int npairs = (N + 1) / 2;

    prep_kernel<<<1, 256>>>(Wt, bt, Wa, ba, Wb, bb);

    int blocks = (npairs + 255) / 256;
    dmasif_main_kernel<<<blocks, 256>>>(features, out, npairs, N);
}

// round 2
// speedup vs baseline: 1.2693x; 1.2693x over previous
#include <cuda_runtime.h>

#define CI 16
#define CO 16

// W1 = Wa @ Wt (fused first two linears), b1 = Wa @ bt + ba. Filled by prep kernel.
__device__ float g_W1[CO * CI];
__device__ float g_b1[CO];

__global__ void prep_kernel(const float* __restrict__ Wt, const float* __restrict__ bt,
                            const float* __restrict__ Wa, const float* __restrict__ ba)
{
    int t = threadIdx.x;              // 256 threads, t = j*16 + i
    int j = t >> 4;
    int i = t & 15;

    float w = 0.0f;
#pragma unroll
    for (int o = 0; o < CO; ++o)
        w = fmaf(Wa[j * CO + o], Wt[o * CI + i], w);
    g_W1[j * CI + i] = w;

    if (i == 0) {
        float b = ba[j];
#pragma unroll
        for (int o = 0; o < CO; ++o)
            b = fmaf(Wa[j * CO + o], bt[o], b);
        g_b1[j] = b;
    }
}

// Packed dual-fp32 FMA (sm_100+). ptxas never emits this from C++; inline PTX only.
__device__ __forceinline__ float2 ffma2(float2 a, float2 b, float2 c)
{
    unsigned long long au, bu, cu, du;
    au = *reinterpret_cast<unsigned long long*>(&a);
    bu = *reinterpret_cast<unsigned long long*>(&b);
    cu = *reinterpret_cast<unsigned long long*>(&c);
    asm("fma.rn.f32x2 %0, %1, %2, %3;" : "=l"(du) : "l"(au), "l"(bu), "l"(cu));
    return *reinterpret_cast<float2*>(&du);
}

__global__ void __launch_bounds__(128)
dmasif_main_kernel(const float* __restrict__ X, const float* __restrict__ Wb,
                   const float* __restrict__ bb, float* __restrict__ Y,
                   int npairs, int N)
{
    __shared__ float sW1[CO * CI];
    __shared__ float sW2[CO * CO];
    __shared__ float sb1[CO];
    __shared__ float sb2[CO];

    int tid = threadIdx.x;
    sW1[tid]       = g_W1[tid];
    sW1[tid + 128] = g_W1[tid + 128];
    sW2[tid]       = Wb[tid];
    sW2[tid + 128] = Wb[tid + 128];
    if (tid < CO) { sb1[tid] = g_b1[tid]; sb2[tid] = bb[tid]; }
    __syncthreads();

    int t = blockIdx.x * 128 + tid;
    if (t >= npairs) return;

    long long r0 = 2LL * t;
    bool hasB = (r0 + 1 < (long long)N);
    long long r1 = hasB ? r0 + 1 : r0;

    const float4* p0 = reinterpret_cast<const float4*>(X + r0 * CI);
    const float4* p1 = reinterpret_cast<const float4*>(X + r1 * CI);

    // Channel-pair packing: xa[i] = {x[2i], x[2i+1]} — natural register pairs, no MOVs.
    float2 xa[8], xb[8];
#pragma unroll
    for (int k = 0; k < 4; ++k) {
        float4 a = p0[k];
        xa[2 * k]     = make_float2(a.x, a.y);
        xa[2 * k + 1] = make_float2(a.z, a.w);
        float4 b = p1[k];
        xb[2 * k]     = make_float2(b.x, b.y);
        xb[2 * k + 1] = make_float2(b.z, b.w);
    }

    // ---- GEMM1 (fused): h = relu(x @ W1^T + b1), two points per thread ----
    float2 h2a[8], h2b[8];
    const float4* W1v = reinterpret_cast<const float4*>(sW1);
#pragma unroll
    for (int j = 0; j < CO; ++j) {
        float4 w0 = W1v[4 * j + 0];
        float4 w1 = W1v[4 * j + 1];
        float4 w2 = W1v[4 * j + 2];
        float4 w3 = W1v[4 * j + 3];
        float2 wv[8] = { {w0.x, w0.y}, {w0.z, w0.w}, {w1.x, w1.y}, {w1.z, w1.w},
                         {w2.x, w2.y}, {w2.z, w2.w}, {w3.x, w3.y}, {w3.z, w3.w} };
        float bj = sb1[j];
        float2 acca = make_float2(bj, 0.0f);
        float2 accb = make_float2(bj, 0.0f);
#pragma unroll
        for (int i = 0; i < 8; ++i) {
            acca = ffma2(xa[i], wv[i], acca);
            accb = ffma2(xb[i], wv[i], accb);
        }
        float va = fmaxf(acca.x + acca.y, 0.0f);
        float vb = fmaxf(accb.x + accb.y, 0.0f);
        if (j & 1) { h2a[j >> 1].y = va; h2b[j >> 1].y = vb; }
        else       { h2a[j >> 1].x = va; h2b[j >> 1].x = vb; }
    }

    // ---- GEMM2: out = h @ Wb^T + bb ----
    float oa[CO], ob[CO];
    const float4* W2v = reinterpret_cast<const float4*>(sW2);
#pragma unroll
    for (int m = 0; m < CO; ++m) {
        float4 w0 = W2v[4 * m + 0];
        float4 w1 = W2v[4 * m + 1];
        float4 w2 = W2v[4 * m + 2];
        float4 w3 = W2v[4 * m + 3];
        float2 wv[8] = { {w0.x, w0.y}, {w0.z, w0.w}, {w1.x, w1.y}, {w1.z, w1.w},
                         {w2.x, w2.y}, {w2.z, w2.w}, {w3.x, w3.y}, {w3.z, w3.w} };
        float bm = sb2[m];
        float2 acca = make_float2(bm, 0.0f);
        float2 accb = make_float2(bm, 0.0f);
#pragma unroll
        for (int i = 0; i < 8; ++i) {
            acca = ffma2(h2a[i], wv[i], acca);
            accb = ffma2(h2b[i], wv[i], accb);
        }
        oa[m] = acca.x + acca.y;
        ob[m] = accb.x + accb.y;
    }

    // ---- Stores (vectorized) ----
    float4* y0 = reinterpret_cast<float4*>(Y + r0 * CO);
    y0[0] = make_float4(oa[0],  oa[1],  oa[2],  oa[3]);
    y0[1] = make_float4(oa[4],  oa[5],  oa[6],  oa[7]);
    y0[2] = make_float4(oa[8],  oa[9],  oa[10], oa[11]);
    y0[3] = make_float4(oa[12], oa[13], oa[14], oa[15]);

    if (hasB) {
        float4* y1 = reinterpret_cast<float4*>(Y + r1 * CO);
        y1[0] = make_float4(ob[0],  ob[1],  ob[2],  ob[3]);
        y1[1] = make_float4(ob[4],  ob[5],  ob[6],  ob[7]);
        y1[2] = make_float4(ob[8],  ob[9],  ob[10], ob[11]);
        y1[3] = make_float4(ob[12], ob[13], ob[14], ob[15]);
    }
}

extern "C" void kernel_launch(void* const* d_in, const int* in_sizes, int n_in,
                              void* d_out, int out_size)
{
    // input order: features, points, nuv, Wt, bt, Wa, ba, Wb, bb, ranges
    const float* features = (const float*)d_in[0];
    const float* Wt = (const float*)d_in[3];
    const float* bt = (const float*)d_in[4];
    const float* Wa = (const float*)d_in[5];
    const float* ba = (const float*)d_in[6];
    const float* Wb = (const float*)d_in[7];
    const float* bb = (const float*)d_in[8];
    float* out = (float*)d_out;

    int N = in_sizes[0] / CI;
    int npairs = (N + 1) / 2;

    prep_kernel<<<1, 256>>>(Wt, bt, Wa, ba);

    int blocks = (npairs + 127) / 128;
    dmasif_main_kernel<<<blocks, 128>>>(features, Wb, bb, out, npairs, N);
}

// round 3
// speedup vs baseline: 1.3171x; 1.0377x over previous
#include <cuda_runtime.h>

#define CI 16
#define CO 16

// W1 = Wa @ Wt (fused first two linears), b1 = Wa @ bt + ba. Filled by prep kernel.
__device__ float g_W1[CO * CI];
__device__ float g_b1[CO];

__global__ void prep_kernel(const float* __restrict__ Wt, const float* __restrict__ bt,
                            const float* __restrict__ Wa, const float* __restrict__ ba)
{
    int t = threadIdx.x;              // 256 threads, t = j*16 + i
    int j = t >> 4;
    int i = t & 15;

    float w = 0.0f;
#pragma unroll
    for (int o = 0; o < CO; ++o)
        w = fmaf(Wa[j * CO + o], Wt[o * CI + i], w);
    g_W1[j * CI + i] = w;

    if (i == 0) {
        float b = ba[j];
#pragma unroll
        for (int o = 0; o < CO; ++o)
            b = fmaf(Wa[j * CO + o], bt[o], b);
        g_b1[j] = b;
    }
}

// Packed dual-fp32 FMA (sm_100+). ptxas never emits this from C++; inline PTX only.
__device__ __forceinline__ float2 ffma2(float2 a, float2 b, float2 c)
{
    unsigned long long au, bu, cu, du;
    au = *reinterpret_cast<unsigned long long*>(&a);
    bu = *reinterpret_cast<unsigned long long*>(&b);
    cu = *reinterpret_cast<unsigned long long*>(&c);
    asm("fma.rn.f32x2 %0, %1, %2, %3;" : "=l"(du) : "l"(au), "l"(bu), "l"(cu));
    return *reinterpret_cast<float2*>(&du);
}

__global__ void __launch_bounds__(128, 6)
dmasif_main_kernel(const float* __restrict__ X, const float* __restrict__ Wb,
                   const float* __restrict__ bb, float* __restrict__ Y,
                   int npairs, int N)
{
    __shared__ float sW1[CO * CI];
    __shared__ float sW2[CO * CO];
    __shared__ float sb1[CO];
    __shared__ float sb2[CO];

    int tid = threadIdx.x;
    sW1[tid]       = g_W1[tid];
    sW1[tid + 128] = g_W1[tid + 128];
    sW2[tid]       = Wb[tid];
    sW2[tid + 128] = Wb[tid + 128];
    if (tid < CO) { sb1[tid] = g_b1[tid]; sb2[tid] = bb[tid]; }
    __syncthreads();

    int t = blockIdx.x * 128 + tid;
    if (t >= npairs) return;

    size_t r0 = 2ull * (unsigned)t;
    bool hasB = ((long long)r0 + 1 < (long long)N);
    size_t r1 = hasB ? r0 + 1 : r0;

    const float4* p0 = reinterpret_cast<const float4*>(X + r0 * CI);
    const float4* p1 = reinterpret_cast<const float4*>(X + r1 * CI);

    // Channel-pair packing: xa[i] = {x[2i], x[2i+1]} — natural register pairs.
    float2 xa[8], xb[8];
#pragma unroll
    for (int k = 0; k < 4; ++k) {
        float4 a = __ldcs(p0 + k);
        xa[2 * k]     = make_float2(a.x, a.y);
        xa[2 * k + 1] = make_float2(a.z, a.w);
        float4 b = __ldcs(p1 + k);
        xb[2 * k]     = make_float2(b.x, b.y);
        xb[2 * k + 1] = make_float2(b.z, b.w);
    }

    // ---- GEMM1 (fused): h = relu(x @ W1^T + b1), two points per thread ----
    float2 h2a[8], h2b[8];
    const float4* W1v = reinterpret_cast<const float4*>(sW1);
#pragma unroll
    for (int j = 0; j < CO; ++j) {
        float2 acca = make_float2(sb1[j], 0.0f);
        float2 accb = make_float2(acca.x, 0.0f);
        // first 8 input channels
        {
            float4 w0 = W1v[4 * j + 0];
            float4 w1 = W1v[4 * j + 1];
            float2 wv0 = make_float2(w0.x, w0.y), wv1 = make_float2(w0.z, w0.w);
            float2 wv2 = make_float2(w1.x, w1.y), wv3 = make_float2(w1.z, w1.w);
            acca = ffma2(xa[0], wv0, acca); accb = ffma2(xb[0], wv0, accb);
            acca = ffma2(xa[1], wv1, acca); accb = ffma2(xb[1], wv1, accb);
            acca = ffma2(xa[2], wv2, acca); accb = ffma2(xb[2], wv2, accb);
            acca = ffma2(xa[3], wv3, acca); accb = ffma2(xb[3], wv3, accb);
        }
        // last 8 input channels
        {
            float4 w2 = W1v[4 * j + 2];
            float4 w3 = W1v[4 * j + 3];
            float2 wv4 = make_float2(w2.x, w2.y), wv5 = make_float2(w2.z, w2.w);
            float2 wv6 = make_float2(w3.x, w3.y), wv7 = make_float2(w3.z, w3.w);
            acca = ffma2(xa[4], wv4, acca); accb = ffma2(xb[4], wv4, accb);
            acca = ffma2(xa[5], wv5, acca); accb = ffma2(xb[5], wv5, accb);
            acca = ffma2(xa[6], wv6, acca); accb = ffma2(xb[6], wv6, accb);
            acca = ffma2(xa[7], wv7, acca); accb = ffma2(xb[7], wv7, accb);
        }
        float va = fmaxf(acca.x + acca.y, 0.0f);
        float vb = fmaxf(accb.x + accb.y, 0.0f);
        if (j & 1) { h2a[j >> 1].y = va; h2b[j >> 1].y = vb; }
        else       { h2a[j >> 1].x = va; h2b[j >> 1].x = vb; }
    }

    // ---- GEMM2 streamed: compute 4 outputs per point, store, free regs ----
    float4* y0 = reinterpret_cast<float4*>(Y + r0 * CO);
    float4* y1 = reinterpret_cast<float4*>(Y + r1 * CO);
    const float4* W2v = reinterpret_cast<const float4*>(sW2);

#pragma unroll
    for (int mc = 0; mc < 4; ++mc) {
        float oa4[4], ob4[4];
#pragma unroll
        for (int mi = 0; mi < 4; ++mi) {
            int m = mc * 4 + mi;
            float2 acca = make_float2(sb2[m], 0.0f);
            float2 accb = make_float2(acca.x, 0.0f);
            {
                float4 w0 = W2v[4 * m + 0];
                float4 w1 = W2v[4 * m + 1];
                float2 wv0 = make_float2(w0.x, w0.y), wv1 = make_float2(w0.z, w0.w);
                float2 wv2 = make_float2(w1.x, w1.y), wv3 = make_float2(w1.z, w1.w);
                acca = ffma2(h2a[0], wv0, acca); accb = ffma2(h2b[0], wv0, accb);
                acca = ffma2(h2a[1], wv1, acca); accb = ffma2(h2b[1], wv1, accb);
                acca = ffma2(h2a[2], wv2, acca); accb = ffma2(h2b[2], wv2, accb);
                acca = ffma2(h2a[3], wv3, acca); accb = ffma2(h2b[3], wv3, accb);
            }
            {
                float4 w2 = W2v[4 * m + 2];
                float4 w3 = W2v[4 * m + 3];
                float2 wv4 = make_float2(w2.x, w2.y), wv5 = make_float2(w2.z, w2.w);
                float2 wv6 = make_float2(w3.x, w3.y), wv7 = make_float2(w3.z, w3.w);
                acca = ffma2(h2a[4], wv4, acca); accb = ffma2(h2b[4], wv4, accb);
                acca = ffma2(h2a[5], wv5, acca); accb = ffma2(h2b[5], wv5, accb);
                acca = ffma2(h2a[6], wv6, acca); accb = ffma2(h2b[6], wv6, accb);
                acca = ffma2(h2a[7], wv7, acca); accb = ffma2(h2b[7], wv7, accb);
            }
            oa4[mi] = acca.x + acca.y;
            ob4[mi] = accb.x + accb.y;
        }
        __stcs(y0 + mc, make_float4(oa4[0], oa4[1], oa4[2], oa4[3]));
        if (hasB)
            __stcs(y1 + mc, make_float4(ob4[0], ob4[1], ob4[2], ob4[3]));
    }
}

extern "C" void kernel_launch(void* const* d_in, const int* in_sizes, int n_in,
                              void* d_out, int out_size)
{
    // input order: features, points, nuv, Wt, bt, Wa, ba, Wb, bb, ranges
    const float* features = (const float*)d_in[0];
    const float* Wt = (const float*)d_in[3];
    const float* bt = (const float*)d_in[4];
    const float* Wa = (const float*)d_in[5];
    const float* ba = (const float*)d_in[6];
    const float* Wb = (const float*)d_in[7];
    const float* bb = (const float*)d_in[8];
    float* out = (float*)d_out;

    int N = in_sizes[0] / CI;
    int npairs = (N + 1) / 2;

    prep_kernel<<<1, 256>>>(Wt, bt, Wa, ba);

    int blocks = (npairs + 127) / 128;
    dmasif_main_kernel<<<blocks, 128>>>(features, Wb, bb, out, npairs, N);
}